// round 3
// baseline (speedup 1.0000x reference)
#include <cuda_runtime.h>
#include <math_constants.h>

#define NPTS 4096
#define WARPS_PER_BLOCK 16
#define NTHREADS (WARPS_PER_BLOCK * 32)
#define FULL 0xffffffffu
#define MARGIN 1e-2f

typedef unsigned long long ull;

__device__ __forceinline__ ull pack2(float x, float y) {
    ull r; asm("mov.b64 %0, {%1, %2};" : "=l"(r) : "f"(x), "f"(y)); return r;
}
__device__ __forceinline__ float2 unpk(ull v) {
    float2 r; asm("mov.b64 {%0, %1}, %2;" : "=f"(r.x), "=f"(r.y) : "l"(v)); return r;
}
__device__ __forceinline__ ull fma2(ull a, ull b, ull c) {
    ull r; asm("fma.rn.f32x2 %0, %1, %2, %3;" : "=l"(r) : "l"(a), "l"(b), "l"(c)); return r;
}

__device__ __forceinline__ bool pless(float da, int ia, float db, int ib) {
    return (da < db) || (da == db && ia < ib);
}
#define CAS(dx, ix, dy, iy)                                  \
    do { if (!pless(dx, ix, dy, iy)) {                       \
        float _t = dx; dx = dy; dy = _t;                     \
        int _u = ix; ix = iy; iy = _u; } } while (0)

__global__ void __launch_bounds__(NTHREADS)
nn_tag_pool_kernel(const float2* __restrict__ obs1,
                   const float2* __restrict__ obs2,
                   const float*  __restrict__ W,
                   const float*  __restrict__ bias,
                   float* __restrict__ out)
{
    __shared__ __align__(16) float sx[NPTS];
    __shared__ __align__(16) float sy[NPTS];
    __shared__ __align__(16) float sn1[NPTS];   // x^2 + y^2 + 1

    const int tid = threadIdx.x;
    {   // stage + deinterleave + precompute norms (amortized over 16 warps)
        const float4* g4 = (const float4*)obs2;
        #pragma unroll
        for (int k = 0; k < 4; ++k) {
            int m = tid + k * NTHREADS;            // float4 index, 2 points each
            float4 v = g4[m];
            int j0 = 2 * m, j1 = j0 + 1;
            sx[j0] = v.x; sy[j0] = v.y; sn1[j0] = fmaf(v.x, v.x, fmaf(v.y, v.y, 1.0f));
            sx[j1] = v.z; sy[j1] = v.w; sn1[j1] = fmaf(v.z, v.z, fmaf(v.w, v.w, 1.0f));
        }
    }
    __syncthreads();

    const int warp = tid >> 5;
    const int lane = tid & 31;
    const int i = blockIdx.x * WARPS_PER_BLOCK + warp;   // query row

    // fused-linear constants (lane = kk*8 + o)
    const int o = lane & 7;
    const float w0 = W[o * 6 + 0];
    const float w1 = W[o * 6 + 1];
    const float w3 = W[o * 6 + 3];
    const float w4 = W[o * 6 + 4];
    const float cb = W[o * 6 + 2] + W[o * 6 + 5] + bias[o];

    const float qx = sx[i], qy = sy[i];
    const float qn = fmaf(qx, qx, qy * qy);       // |q|^2
    const float qnm = qn - MARGIN;
    const ull m2qx2 = pack2(-2.0f * qx, -2.0f * qx);
    const ull m2qy2 = pack2(-2.0f * qy, -2.0f * qy);

    // private per-lane sorted top-4 (exact distances)
    float d0 = CUDART_INF_F, d1 = CUDART_INF_F, d2 = CUDART_INF_F, d3 = CUDART_INF_F;
    int   i0 = 0x7fffffff,  i1 = 0x7fffffff,  i2 = 0x7fffffff,  i3 = 0x7fffffff;

    const ulonglong2* sxp = (const ulonglong2*)sx;   // [m] = x[4m..4m+3] as 2 packed pairs
    const ulonglong2* syp = (const ulonglong2*)sy;
    const ulonglong2* snp = (const ulonglong2*)sn1;

    #pragma unroll 2
    for (int it = 0; it < NPTS / 256; ++it) {     // 16 iters, 8 pts/lane, 256/warp
        // warp-min screen threshold (valid upper bound on true 4th; only decreases)
        const float tauw = __uint_as_float(__reduce_min_sync(FULL, __float_as_uint(d3)));
        const float tm = tauw - qnm;              // screen in d' space, incl. margin

        const int m = it * 64 + lane;
        ulonglong2 XA = sxp[m],      YA = syp[m],      NA = snp[m];
        ulonglong2 XB = sxp[m + 32], YB = syp[m + 32], NB = snp[m + 32];

        // d' = (n+1) - 2 q.p   (2 fma.f32x2 per 2 points)
        ull dA0 = fma2(XA.x, m2qx2, fma2(YA.x, m2qy2, NA.x));
        ull dA1 = fma2(XA.y, m2qx2, fma2(YA.y, m2qy2, NA.y));
        ull dB0 = fma2(XB.x, m2qx2, fma2(YB.x, m2qy2, NB.x));
        ull dB1 = fma2(XB.y, m2qx2, fma2(YB.y, m2qy2, NB.y));

        float2 a0 = unpk(dA0), a1 = unpk(dA1), b0 = unpk(dB0), b1 = unpk(dB1);
        float mn = fminf(fminf(fminf(a0.x, a0.y), fminf(a1.x, a1.y)),
                         fminf(fminf(b0.x, b0.y), fminf(b1.x, b1.y)));

        if (mn <= tm) {   // rare; per-lane private slow path (no shfls)
            const int jA = it * 256 + 4 * lane;        // points jA..jA+3
            const int jB = jA + 128;                   // points jB..jB+3
            float2 pr[4] = {a0, a1, b0, b1};
            int    jb[4] = {jA, jA + 2, jB, jB + 2};
            #pragma unroll
            for (int k = 0; k < 4; ++k) {
                #pragma unroll
                for (int h = 0; h < 2; ++h) {
                    float dpv = h ? pr[k].y : pr[k].x;
                    if (dpv <= tm) {
                        int j = jb[k] + h;
                        float dx = sx[j] - qx, dy = sy[j] - qy;
                        float dv = fmaf(dx, dx, fmaf(dy, dy, 1.0f));  // exact form
                        if (j != i && dv < d3) {   // increasing j within lane => strict < OK
                            d3 = dv; i3 = j;
                            if (d3 < d2) { float t=d3; d3=d2; d2=t; int u=i3; i3=i2; i2=u; }
                            if (d2 < d1) { float t=d2; d2=d1; d1=t; int u=i2; i2=i1; i1=u; }
                            if (d1 < d0) { float t=d1; d1=d0; d0=t; int u=i1; i1=i0; i0=u; }
                        }
                    }
                }
            }
        }
    }

    // butterfly merge of 32 private sorted-4 lists -> warp-uniform global top-4
    #pragma unroll
    for (int off = 16; off >= 1; off >>= 1) {
        float e0 = __shfl_xor_sync(FULL, d0, off);
        float e1 = __shfl_xor_sync(FULL, d1, off);
        float e2 = __shfl_xor_sync(FULL, d2, off);
        float e3 = __shfl_xor_sync(FULL, d3, off);
        int   j0 = __shfl_xor_sync(FULL, i0, off);
        int   j1 = __shfl_xor_sync(FULL, i1, off);
        int   j2 = __shfl_xor_sync(FULL, i2, off);
        int   j3 = __shfl_xor_sync(FULL, i3, off);

        float m0, m1, m2, m3; int n0, n1, n2, n3;
        if (pless(d0, i0, e3, j3)) { m0 = d0; n0 = i0; } else { m0 = e3; n0 = j3; }
        if (pless(d1, i1, e2, j2)) { m1 = d1; n1 = i1; } else { m1 = e2; n1 = j2; }
        if (pless(d2, i2, e1, j1)) { m2 = d2; n2 = i2; } else { m2 = e1; n2 = j1; }
        if (pless(d3, i3, e0, j0)) { m3 = d3; n3 = i3; } else { m3 = e0; n3 = j0; }

        CAS(m0, n0, m2, n2);
        CAS(m1, n1, m3, n3);
        CAS(m0, n0, m1, n1);
        CAS(m2, n2, m3, n3);

        d0 = m0; d1 = m1; d2 = m2; d3 = m3;
        i0 = n0; i1 = n1; i2 = n2; i3 = n3;
    }

    // epilogue: lane kk*8+o computes output channel o of neighbor kk
    const int kk = lane >> 3;
    const int j = (kk == 0) ? i0 : (kk == 1) ? i1 : (kk == 2) ? i2 : i3;

    const float pjx = sx[j], pjy = sy[j];
    const float2 a1j = obs1[j];
    const float2 a1i = obs1[i];

    const float px = pjx - qx;
    const float py = pjy - qy;
    const float vx = (pjx - a1j.x) - (qx - a1i.x);   // vel[j] - vel[i]
    const float vy = (pjy - a1j.y) - (qy - a1i.y);

    float r = fmaf(px, w0, fmaf(py, w1, fmaf(vx, w3, fmaf(vy, w4, cb))));
    out[i * 32 + lane] = fmaxf(r, 0.0f);
}

extern "C" void kernel_launch(void* const* d_in, const int* in_sizes, int n_in,
                              void* d_out, int out_size) {
    const float2* obs1 = (const float2*)d_in[0];
    const float2* obs2 = (const float2*)d_in[1];
    const float*  W    = (const float*)d_in[2];
    const float*  bias = (const float*)d_in[3];
    float* out = (float*)d_out;

    dim3 grid(NPTS / WARPS_PER_BLOCK);   // 256 blocks
    dim3 block(NTHREADS);                // 512 threads = 16 warps
    nn_tag_pool_kernel<<<grid, block>>>(obs1, obs2, W, bias, out);
}

// round 5
// speedup vs baseline: 1.6427x; 1.6427x over previous
#include <cuda_runtime.h>
#include <math_constants.h>

#define NPTS 4096
#define WARPS_PER_BLOCK 28
#define NTHREADS (WARPS_PER_BLOCK * 32)      // 896
#define NBLOCKS 147                           // 147*28 = 4116 >= 4096, 1 block/SM
#define FULL 0xffffffffu

__device__ __forceinline__ void ins4(float dv, int j,
                                     float& d0, float& d1, float& d2, float& d3,
                                     int& i0, int& i1, int& i2, int& i3) {
    // warp-uniform insertion, strictly increasing j across calls, strict '<'
    d3 = dv; i3 = j;
    if (d3 < d2) { float t=d3; d3=d2; d2=t; int u=i3; i3=i2; i2=u; }
    if (d2 < d1) { float t=d2; d2=d1; d1=t; int u=i2; i2=i1; i1=u; }
    if (d1 < d0) { float t=d1; d1=d0; d0=t; int u=i1; i1=i0; i0=u; }
}

__global__ void __launch_bounds__(NTHREADS)
nn_tag_pool_kernel(const float2* __restrict__ obs1,
                   const float2* __restrict__ obs2,
                   const float*  __restrict__ W,
                   const float*  __restrict__ bias,
                   float* __restrict__ out)
{
    __shared__ __align__(16) float sx[NPTS];
    __shared__ __align__(16) float sy[NPTS];

    const int tid = threadIdx.x;
    {   // stage + deinterleave: obs2 AoS float2 -> SoA sx/sy
        const float4* g4 = (const float4*)obs2;
        for (int m = tid; m < NPTS / 2; m += NTHREADS) {
            float4 v = g4[m];                 // {x0,y0,x1,y1}
            sx[2*m]   = v.x;  sy[2*m]   = v.y;
            sx[2*m+1] = v.z;  sy[2*m+1] = v.w;
        }
    }
    __syncthreads();

    const int warp = tid >> 5;
    const int lane = tid & 31;
    const int i = blockIdx.x * WARPS_PER_BLOCK + warp;   // query row
    if (i >= NPTS) return;                    // inactive tail warps (after sync)

    // fused-linear constants (lane = kk*8 + o); tag columns folded into bias
    const int o = lane & 7;
    const float w0 = W[o * 6 + 0];
    const float w1 = W[o * 6 + 1];
    const float w3 = W[o * 6 + 3];
    const float w4 = W[o * 6 + 4];
    const float cb = W[o * 6 + 2] + W[o * 6 + 5] + bias[o];

    const float qx = sx[i], qy = sy[i];

    // warp-uniform sorted top-4 (ascending dist; ties -> smaller index)
    float d0 = CUDART_INF_F, d1 = CUDART_INF_F, d2 = CUDART_INF_F, d3 = CUDART_INF_F;
    int   i0 = 0, i1 = 0, i2 = 0, i3 = 0;

    const float4* sx4 = (const float4*)sx;
    const float4* sy4 = (const float4*)sy;

    #pragma unroll 4
    for (int it = 0; it < NPTS / 128; ++it) { // 32 iters, 4 pts/lane, 128/warp
        float4 X = sx4[it * 32 + lane];
        float4 Y = sy4[it * 32 + lane];

        float dx0 = X.x - qx, dy0 = Y.x - qy;
        float dx1 = X.y - qx, dy1 = Y.y - qy;
        float dx2 = X.z - qx, dy2 = Y.z - qy;
        float dx3 = X.w - qx, dy3 = Y.w - qy;
        float v0 = fmaf(dx0, dx0, fmaf(dy0, dy0, 1.0f));   // exact dist2
        float v1 = fmaf(dx1, dx1, fmaf(dy1, dy1, 1.0f));
        float v2 = fmaf(dx2, dx2, fmaf(dy2, dy2, 1.0f));
        float v3 = fmaf(dx3, dx3, fmaf(dy3, dy3, 1.0f));
        float mn = fminf(fminf(v0, v1), fminf(v2, v3));

        unsigned m = __ballot_sync(FULL, mn < d3);
        while (m) {                            // warp-uniform (m uniform)
            int r = __ffs(m) - 1;
            m &= m - 1;
            float x0 = __shfl_sync(FULL, v0, r);
            float x1 = __shfl_sync(FULL, v1, r);
            float x2 = __shfl_sync(FULL, v2, r);
            float x3 = __shfl_sync(FULL, v3, r);
            int jb = (it * 32 + r) * 4;        // candidates jb..jb+3, ascending

            if (jb + 0 != i && x0 < d3) ins4(x0, jb + 0, d0,d1,d2,d3, i0,i1,i2,i3);
            if (jb + 1 != i && x1 < d3) ins4(x1, jb + 1, d0,d1,d2,d3, i0,i1,i2,i3);
            if (jb + 2 != i && x2 < d3) ins4(x2, jb + 2, d0,d1,d2,d3, i0,i1,i2,i3);
            if (jb + 3 != i && x3 < d3) ins4(x3, jb + 3, d0,d1,d2,d3, i0,i1,i2,i3);

            if (m) m &= __ballot_sync(FULL, mn < d3);  // refilter vs tighter d3
        }
    }

    // list is warp-uniform: no merge. lane kk*8+o -> channel o of neighbor kk
    const int kk = lane >> 3;
    const int j = (kk == 0) ? i0 : (kk == 1) ? i1 : (kk == 2) ? i2 : i3;

    const float pjx = sx[j], pjy = sy[j];
    const float2 a1j = obs1[j];
    const float2 a1i = obs1[i];

    const float px = pjx - qx;
    const float py = pjy - qy;
    const float vx = (pjx - a1j.x) - (qx - a1i.x);   // vel[j] - vel[i]
    const float vy = (pjy - a1j.y) - (qy - a1i.y);

    float r = fmaf(px, w0, fmaf(py, w1, fmaf(vx, w3, fmaf(vy, w4, cb))));
    out[i * 32 + lane] = fmaxf(r, 0.0f);
}

extern "C" void kernel_launch(void* const* d_in, const int* in_sizes, int n_in,
                              void* d_out, int out_size) {
    const float2* obs1 = (const float2*)d_in[0];
    const float2* obs2 = (const float2*)d_in[1];
    const float*  W    = (const float*)d_in[2];
    const float*  bias = (const float*)d_in[3];
    float* out = (float*)d_out;

    nn_tag_pool_kernel<<<NBLOCKS, NTHREADS>>>(obs1, obs2, W, bias, out);
}